// round 2
// baseline (speedup 1.0000x reference)
#include <cuda_runtime.h>
#include <cuda_bf16.h>
#include <mma.h>

using namespace nvcuda;

#define K_CLS 10
#define P 128
#define CAP 262144          // max rows (m)
#define EPS_C 0.01f
#define KT 64               // rows per gram tile
#define BPC 15              // blocks per class

// ---------------- device globals (no allocations allowed) ----------------
__device__ int   d_cursor[K_CLS];              // per-class counts / cursors
__device__ int   d_idx[K_CLS * CAP];           // per-class row index lists
__device__ float d_cov[K_CLS * P * P];         // per-class Gram matrices
__device__ float d_logdets[K_CLS + 1];         // [0]=full, [1..10]=classes (= logdet/2)

// ---------------- zero scratch ----------------
__global__ void zero_kernel() {
    int total = K_CLS * P * P;
    for (int i = blockIdx.x * blockDim.x + threadIdx.x; i < total;
         i += gridDim.x * blockDim.x)
        d_cov[i] = 0.0f;
    int t = blockIdx.x * blockDim.x + threadIdx.x;
    if (t < K_CLS) d_cursor[t] = 0;
    if (t < K_CLS + 1) d_logdets[t] = 0.0f;
}

// ---------------- class-partition scatter (index lists + counts) ----------------
__global__ void scatter_kernel(const int* __restrict__ y, int m) {
    __shared__ int sCnt[K_CLS], sBase[K_CLS];
    int tid = threadIdx.x;
    int i = blockIdx.x * blockDim.x + tid;
    if (tid < K_CLS) sCnt[tid] = 0;
    __syncthreads();

    int c = 0, local = 0;
    bool act = (i < m);
    if (act) {
        c = y[i];
        if (c < 0) c = 0;
        if (c >= K_CLS) c = K_CLS - 1;
        unsigned mask = __match_any_sync(__activemask(), c);
        int leader = __ffs(mask) - 1;
        int lane = tid & 31;
        int rank = __popc(mask & ((1u << lane) - 1));
        int wb = 0;
        if (lane == leader) wb = atomicAdd(&sCnt[c], __popc(mask));
        wb = __shfl_sync(mask, wb, leader);
        local = wb + rank;
    }
    __syncthreads();
    if (tid < K_CLS) sBase[tid] = atomicAdd(&d_cursor[tid], sCnt[tid]);
    __syncthreads();
    if (act) d_idx[c * CAP + sBase[c] + local] = i;
}

// ---------------- per-class Gram via split-bf16 wmma (fp32 accumulate) ----------
// v = hi + lo (both bf16); v_i*v_j ~= hi_i*hi_j + hi_i*lo_j + lo_i*hi_j
// gives ~16+ effective mantissa bits, near-fp32 Gram accuracy.
__global__ void __launch_bounds__(256, 2)
gram_kernel(const float* __restrict__ x) {
    int c = blockIdx.y;
    int n = d_cursor[c];
    const int* idx = d_idx + c * CAP;

    __shared__ __nv_bfloat16 sH[KT][P];   // 16 KB  (hi part)
    __shared__ __nv_bfloat16 sL[KT][P];   // 16 KB  (lo part)
    __shared__ int sIdx[KT];
    __shared__ float sOut[8][256];        // 8 KB per-warp staging

    int tid = threadIdx.x;
    int w = tid >> 5;
    int lane = tid & 31;

    wmma::fragment<wmma::matrix_a, 16, 16, 16, __nv_bfloat16, wmma::col_major> faH, faL;
    wmma::fragment<wmma::matrix_b, 16, 16, 16, __nv_bfloat16, wmma::row_major> fbH, fbL;
    wmma::fragment<wmma::accumulator, 16, 16, 16, float> acc[8];
#pragma unroll
    for (int t = 0; t < 8; t++) wmma::fill_fragment(acc[t], 0.0f);

    for (int j0 = blockIdx.x * KT; j0 < n; j0 += BPC * KT) {
        __syncthreads();
        if (tid < KT) sIdx[tid] = (j0 + tid < n) ? idx[j0 + tid] : -1;
        __syncthreads();
        // gather rows (fp32), split into hi/lo bf16
#pragma unroll
        for (int q = 0; q < 8; q++) {
            int u = tid + q * 256;        // float4 unit index, 2048 total
            int r = u >> 5;               // row within tile
            int c4 = u & 31;              // float4 within row
            int g = sIdx[r];
            float4 v = (g >= 0) ? reinterpret_cast<const float4*>(x)[g * 32 + c4]
                                : make_float4(0.f, 0.f, 0.f, 0.f);
            __nv_bfloat16 hx = __float2bfloat16_rn(v.x);
            __nv_bfloat16 hy = __float2bfloat16_rn(v.y);
            __nv_bfloat16 hz = __float2bfloat16_rn(v.z);
            __nv_bfloat16 hw = __float2bfloat16_rn(v.w);
            __nv_bfloat16 lx = __float2bfloat16_rn(v.x - __bfloat162float(hx));
            __nv_bfloat16 ly = __float2bfloat16_rn(v.y - __bfloat162float(hy));
            __nv_bfloat16 lz = __float2bfloat16_rn(v.z - __bfloat162float(hz));
            __nv_bfloat16 lw = __float2bfloat16_rn(v.w - __bfloat162float(hw));
            *reinterpret_cast<__nv_bfloat162*>(&sH[r][c4 * 4])     = __nv_bfloat162(hx, hy);
            *reinterpret_cast<__nv_bfloat162*>(&sH[r][c4 * 4 + 2]) = __nv_bfloat162(hz, hw);
            *reinterpret_cast<__nv_bfloat162*>(&sL[r][c4 * 4])     = __nv_bfloat162(lx, ly);
            *reinterpret_cast<__nv_bfloat162*>(&sL[r][c4 * 4 + 2]) = __nv_bfloat162(lz, lw);
        }
        __syncthreads();
#pragma unroll
        for (int ks = 0; ks < KT / 16; ks++) {
            wmma::load_matrix_sync(faH, &sH[ks * 16][w * 16], P);
            wmma::load_matrix_sync(faL, &sL[ks * 16][w * 16], P);
#pragma unroll
            for (int t = 0; t < 8; t++) {
                wmma::load_matrix_sync(fbH, &sH[ks * 16][t * 16], P);
                wmma::load_matrix_sync(fbL, &sL[ks * 16][t * 16], P);
                wmma::mma_sync(acc[t], faH, fbH, acc[t]);
                wmma::mma_sync(acc[t], faH, fbL, acc[t]);
                wmma::mma_sync(acc[t], faL, fbH, acc[t]);
            }
        }
    }

    // epilogue: per-warp staging -> global atomics
    float* covc = d_cov + c * P * P;
#pragma unroll
    for (int t = 0; t < 8; t++) {
        wmma::store_matrix_sync(&sOut[w][0], acc[t], 16, wmma::mem_row_major);
        __syncwarp();
        for (int e = lane; e < 256; e += 32) {
            int r = w * 16 + (e >> 4);
            int col = t * 16 + (e & 15);
            atomicAdd(&covc[r * P + col], sOut[w][e]);
        }
        __syncwarp();
    }
}

// ---------------- Cholesky logdet (one block per matrix) ----------------
// Column-major A[col*128 + row] in dynamic smem; left-looking.
__global__ void chol_kernel(int m) {
    extern __shared__ float A[];  // 128*128 floats = 64 KB
    int b = blockIdx.x;
    int i = threadIdx.x;          // 128 threads, thread == row

    if (b == 0) {
        float scal = (float)P / ((float)m * EPS_C);
        for (int e = i; e < P * P; e += 128) {
            float v = 0.f;
#pragma unroll
            for (int c = 0; c < K_CLS; c++) v += d_cov[c * P * P + e];
            A[e] = ((e % (P + 1)) == 0 ? 1.0f : 0.0f) + scal * v;
        }
    } else {
        int c = b - 1;
        int n = d_cursor[c];
        int ns = n > 0 ? n : 1;
        float scal = (float)P / ((float)ns * EPS_C);
        for (int e = i; e < P * P; e += 128)
            A[e] = ((e % (P + 1)) == 0 ? 1.0f : 0.0f) + scal * d_cov[c * P * P + e];
    }
    __syncthreads();

    float logsum = 0.0f;
    for (int j = 0; j < P; j++) {
        float s = 0.0f;
        if (i >= j) {
            s = A[j * P + i];
            float a0 = 0.f, a1 = 0.f, a2 = 0.f, a3 = 0.f;
            int t = 0;
            for (; t + 3 < j; t += 4) {
                a0 += A[(t + 0) * P + i] * A[(t + 0) * P + j];
                a1 += A[(t + 1) * P + i] * A[(t + 1) * P + j];
                a2 += A[(t + 2) * P + i] * A[(t + 2) * P + j];
                a3 += A[(t + 3) * P + i] * A[(t + 3) * P + j];
            }
            for (; t < j; t++) a0 += A[t * P + i] * A[t * P + j];
            s -= (a0 + a1) + (a2 + a3);
            A[j * P + i] = s;
        }
        __syncthreads();
        float d = sqrtf(A[j * P + j]);
        logsum += logf(d);
        if (i > j)       A[j * P + i] = s / d;
        else if (i == j) A[j * P + i] = d;
        __syncthreads();
    }
    if (i == 0) d_logdets[b] = logsum;   // = slogdet/2
}

// ---------------- final reduction to 4 scalars ----------------
__global__ void finalize_kernel(float* __restrict__ out, int m) {
    if (threadIdx.x == 0 && blockIdx.x == 0) {
        float disc = d_logdets[0];   // discrimn_empi == discrimn_theo (GAM1 = 1)
        float comp = 0.0f;
#pragma unroll
        for (int c = 0; c < K_CLS; c++) {
            int n = d_cursor[c];
            if (n > 0) comp += d_logdets[1 + c] * ((float)n / (float)m);
        }
        out[0] = -disc + comp;  // GAM2 = 1
        out[1] = disc;
        out[2] = disc;
        out[3] = comp;
    }
}

// ---------------- launch ----------------
extern "C" void kernel_launch(void* const* d_in, const int* in_sizes, int n_in,
                              void* d_out, int out_size) {
    const float* x = (const float*)d_in[0];
    const int*   y = (const int*)d_in[1];
    int m = in_sizes[0] / P;

    cudaFuncSetAttribute(chol_kernel,
                         cudaFuncAttributeMaxDynamicSharedMemorySize, 65536);

    zero_kernel<<<256, 256>>>();
    scatter_kernel<<<(m + 255) / 256, 256>>>(y, m);
    gram_kernel<<<dim3(BPC, K_CLS), 256>>>(x);
    chol_kernel<<<K_CLS + 1, P, 65536>>>(m);
    finalize_kernel<<<1, 32>>>((float*)d_out, m);
}

// round 3
// speedup vs baseline: 1.0594x; 1.0594x over previous
#include <cuda_runtime.h>
#include <cuda_bf16.h>
#include <mma.h>

using namespace nvcuda;

#define K_CLS 10
#define P 128
#define CAP 262144          // max rows (m)
#define EPS_C 0.01f
#define KT 64               // rows per gram tile
#define BPC 14              // blocks per class (14*10=140 <= 148 SMs, one wave)
#define LDP 132             // padded row stride for Cholesky smem (floats)

// ---------------- device globals (no allocations allowed) ----------------
__device__ int   d_cursor[K_CLS];              // per-class counts / cursors
__device__ int   d_idx[K_CLS * CAP];           // per-class row index lists
__device__ float d_cov[K_CLS * P * P];         // per-class Gram matrices
__device__ float d_logdets[K_CLS + 1];         // [0]=full, [1..10]=classes (= logdet/2)

// ---------------- zero scratch ----------------
__global__ void zero_kernel() {
    int total = K_CLS * P * P;
    for (int i = blockIdx.x * blockDim.x + threadIdx.x; i < total;
         i += gridDim.x * blockDim.x)
        d_cov[i] = 0.0f;
    int t = blockIdx.x * blockDim.x + threadIdx.x;
    if (t < K_CLS) d_cursor[t] = 0;
    if (t < K_CLS + 1) d_logdets[t] = 0.0f;
}

// ---------------- class-partition scatter (index lists + counts) ----------------
__global__ void scatter_kernel(const int* __restrict__ y, int m) {
    __shared__ int sCnt[K_CLS], sBase[K_CLS];
    int tid = threadIdx.x;
    int i = blockIdx.x * blockDim.x + tid;
    if (tid < K_CLS) sCnt[tid] = 0;
    __syncthreads();

    int c = 0, local = 0;
    bool act = (i < m);
    if (act) {
        c = y[i];
        if (c < 0) c = 0;
        if (c >= K_CLS) c = K_CLS - 1;
        unsigned mask = __match_any_sync(__activemask(), c);
        int leader = __ffs(mask) - 1;
        int lane = tid & 31;
        int rank = __popc(mask & ((1u << lane) - 1));
        int wb = 0;
        if (lane == leader) wb = atomicAdd(&sCnt[c], __popc(mask));
        wb = __shfl_sync(mask, wb, leader);
        local = wb + rank;
    }
    __syncthreads();
    if (tid < K_CLS) sBase[tid] = atomicAdd(&d_cursor[tid], sCnt[tid]);
    __syncthreads();
    if (act) d_idx[c * CAP + sBase[c] + local] = i;
}

// ---------------- per-class Gram via split-bf16 wmma, symmetric 2-MMA ----------
// v = hi + lo (both bf16).  cov = H^T H + H^T L + (H^T L)^T.
// Compute C1 = H^T H and C2 = H^T L; epilogue adds C2 both straight and
// transposed (bitwise identical to accumulating L^T H separately).
// 512 threads = 16 warps: warp w -> rows 16*(w&7), column half (w>>3)*64.
__global__ void __launch_bounds__(512, 1)
gram_kernel(const float* __restrict__ x) {
    int c = blockIdx.y;
    int n = d_cursor[c];
    const int* idx = d_idx + c * CAP;

    __shared__ __nv_bfloat16 sH[KT][P];   // 16 KB  (hi part)
    __shared__ __nv_bfloat16 sL[KT][P];   // 16 KB  (lo part)
    __shared__ int sIdx[KT];

    int tid = threadIdx.x;
    int w = tid >> 5;
    int lane = tid & 31;
    int wr = w & 7;        // output row strip: rows [16*wr, 16*wr+16)
    int wc = w >> 3;       // column half: cols [64*wc, 64*wc+64)

    wmma::fragment<wmma::matrix_a, 16, 16, 16, __nv_bfloat16, wmma::col_major> faH;
    wmma::fragment<wmma::matrix_b, 16, 16, 16, __nv_bfloat16, wmma::row_major> fbH, fbL;
    wmma::fragment<wmma::accumulator, 16, 16, 16, float> accH[4], accL[4];
#pragma unroll
    for (int t = 0; t < 4; t++) {
        wmma::fill_fragment(accH[t], 0.0f);
        wmma::fill_fragment(accL[t], 0.0f);
    }

    for (int j0 = blockIdx.x * KT; j0 < n; j0 += BPC * KT) {
        __syncthreads();
        if (tid < KT) sIdx[tid] = (j0 + tid < n) ? idx[j0 + tid] : -1;
        __syncthreads();
        // gather rows (fp32), split into hi/lo bf16.  2048 float4 units.
#pragma unroll
        for (int q = 0; q < 4; q++) {
            int u = tid + q * 512;
            int r = u >> 5;               // row within tile
            int c4 = u & 31;              // float4 within row
            int g = sIdx[r];
            float4 v = (g >= 0) ? reinterpret_cast<const float4*>(x)[g * 32 + c4]
                                : make_float4(0.f, 0.f, 0.f, 0.f);
            __nv_bfloat16 hx = __float2bfloat16_rn(v.x);
            __nv_bfloat16 hy = __float2bfloat16_rn(v.y);
            __nv_bfloat16 hz = __float2bfloat16_rn(v.z);
            __nv_bfloat16 hw = __float2bfloat16_rn(v.w);
            __nv_bfloat16 lx = __float2bfloat16_rn(v.x - __bfloat162float(hx));
            __nv_bfloat16 ly = __float2bfloat16_rn(v.y - __bfloat162float(hy));
            __nv_bfloat16 lz = __float2bfloat16_rn(v.z - __bfloat162float(hz));
            __nv_bfloat16 lw = __float2bfloat16_rn(v.w - __bfloat162float(hw));
            *reinterpret_cast<__nv_bfloat162*>(&sH[r][c4 * 4])     = __nv_bfloat162(hx, hy);
            *reinterpret_cast<__nv_bfloat162*>(&sH[r][c4 * 4 + 2]) = __nv_bfloat162(hz, hw);
            *reinterpret_cast<__nv_bfloat162*>(&sL[r][c4 * 4])     = __nv_bfloat162(lx, ly);
            *reinterpret_cast<__nv_bfloat162*>(&sL[r][c4 * 4 + 2]) = __nv_bfloat162(lz, lw);
        }
        __syncthreads();
#pragma unroll
        for (int ks = 0; ks < KT / 16; ks++) {
            wmma::load_matrix_sync(faH, &sH[ks * 16][wr * 16], P);
#pragma unroll
            for (int t = 0; t < 4; t++) {
                int tc = wc * 64 + t * 16;
                wmma::load_matrix_sync(fbH, &sH[ks * 16][tc], P);
                wmma::load_matrix_sync(fbL, &sL[ks * 16][tc], P);
                wmma::mma_sync(accH[t], faH, fbH, accH[t]);
                wmma::mma_sync(accL[t], faH, fbL, accL[t]);
            }
        }
    }

    // epilogue: stage per-warp through smem (reuse sH after sync) -> atomics
    __syncthreads();
    float* stage = reinterpret_cast<float*>(&sH[0][0]) + w * 256;  // 16 warps * 1KB
    float* covc = d_cov + c * P * P;
#pragma unroll
    for (int t = 0; t < 4; t++) {
        int cbase = wc * 64 + t * 16;
        // C1 = H^T H
        wmma::store_matrix_sync(stage, accH[t], 16, wmma::mem_row_major);
        __syncwarp();
        for (int e = lane; e < 256; e += 32) {
            int r = wr * 16 + (e >> 4);
            int col = cbase + (e & 15);
            atomicAdd(&covc[r * P + col], stage[e]);
        }
        __syncwarp();
        // C2 = H^T L, added straight and transposed
        wmma::store_matrix_sync(stage, accL[t], 16, wmma::mem_row_major);
        __syncwarp();
        for (int e = lane; e < 256; e += 32) {
            int r = wr * 16 + (e >> 4);
            int col = cbase + (e & 15);
            float v = stage[e];
            atomicAdd(&covc[r * P + col], v);
            atomicAdd(&covc[col * P + r], v);
        }
        __syncwarp();
    }
}

// ---------------- Cholesky logdet (one block per matrix) ----------------
// Row-major padded A[i*LDP + t] in dynamic smem. Dot products over own row
// (contiguous float4, conflict-free via +4 pad) and pivot row (broadcast).
__global__ void __launch_bounds__(128) chol_kernel(int m) {
    extern __shared__ float A[];  // 128*132 floats = 67.6 KB
    __shared__ float sDiag;
    int b = blockIdx.x;
    int i = threadIdx.x;          // thread == row

    if (b == 0) {
        float scal = (float)P / ((float)m * EPS_C);
        for (int e = i; e < P * P; e += 128) {
            float v = 0.f;
#pragma unroll
            for (int c = 0; c < K_CLS; c++) v += d_cov[c * P * P + e];
            A[(e >> 7) * LDP + (e & 127)] =
                ((e % (P + 1)) == 0 ? 1.0f : 0.0f) + scal * v;
        }
    } else {
        int c = b - 1;
        int n = d_cursor[c];
        int ns = n > 0 ? n : 1;
        float scal = (float)P / ((float)ns * EPS_C);
        for (int e = i; e < P * P; e += 128)
            A[(e >> 7) * LDP + (e & 127)] =
                ((e % (P + 1)) == 0 ? 1.0f : 0.0f) + scal * d_cov[c * P * P + e];
    }
    __syncthreads();

    float logsum = 0.0f;
    for (int j = 0; j < P; j++) {
        float s = 0.0f;
        if (i >= j) {
            const float4* ri = reinterpret_cast<const float4*>(A + i * LDP);
            const float4* rj = reinterpret_cast<const float4*>(A + j * LDP);
            float a0 = 0.f, a1 = 0.f, a2 = 0.f, a3 = 0.f;
            int n4 = j >> 2;
#pragma unroll 4
            for (int t = 0; t < n4; t++) {
                float4 u = ri[t];
                float4 v = rj[t];
                a0 += u.x * v.x; a1 += u.y * v.y;
                a2 += u.z * v.z; a3 += u.w * v.w;
            }
            for (int t = n4 * 4; t < j; t++)
                a0 += A[i * LDP + t] * A[j * LDP + t];
            s = A[i * LDP + j] - ((a0 + a1) + (a2 + a3));
            if (i == j) sDiag = s;
        }
        __syncthreads();
        float dd = sDiag;
        float d = sqrtf(dd);
        logsum += 0.5f * logf(dd);
        if (i > j)       A[i * LDP + j] = s / d;
        else if (i == j) A[i * LDP + j] = d;
        __syncthreads();
    }
    if (i == 0) d_logdets[b] = logsum;   // = slogdet/2
}

// ---------------- final reduction to 4 scalars ----------------
__global__ void finalize_kernel(float* __restrict__ out, int m) {
    if (threadIdx.x == 0 && blockIdx.x == 0) {
        float disc = d_logdets[0];   // discrimn_empi == discrimn_theo (GAM1 = 1)
        float comp = 0.0f;
#pragma unroll
        for (int c = 0; c < K_CLS; c++) {
            int n = d_cursor[c];
            if (n > 0) comp += d_logdets[1 + c] * ((float)n / (float)m);
        }
        out[0] = -disc + comp;  // GAM2 = 1
        out[1] = disc;
        out[2] = disc;
        out[3] = comp;
    }
}

// ---------------- launch ----------------
extern "C" void kernel_launch(void* const* d_in, const int* in_sizes, int n_in,
                              void* d_out, int out_size) {
    const float* x = (const float*)d_in[0];
    const int*   y = (const int*)d_in[1];
    int m = in_sizes[0] / P;

    cudaFuncSetAttribute(chol_kernel,
                         cudaFuncAttributeMaxDynamicSharedMemorySize, 128 * LDP * 4);

    zero_kernel<<<256, 256>>>();
    scatter_kernel<<<(m + 255) / 256, 256>>>(y, m);
    gram_kernel<<<dim3(BPC, K_CLS), 512>>>(x);
    chol_kernel<<<K_CLS + 1, P, 128 * LDP * 4>>>(m);
    finalize_kernel<<<1, 32>>>((float*)d_out, m);
}

// round 4
// speedup vs baseline: 1.0595x; 1.0001x over previous
#include <cuda_runtime.h>
#include <cuda_bf16.h>
#include <mma.h>

using namespace nvcuda;

#define K_CLS 10
#define P 128
#define CAP 262144          // max rows (m)
#define EPS_C 0.01f
#define KT 64               // rows per gram tile
#define BPC 14              // blocks per class (14*10=140 <= 148 SMs, one wave)
#define LDP 132             // padded row stride for Cholesky smem (floats)

// ---------------- device globals (no allocations allowed) ----------------
__device__ int   d_cursor[K_CLS];              // per-class counts / cursors
__device__ int   d_idx[K_CLS * CAP];           // per-class row index lists
__device__ float d_cov[K_CLS * P * P];         // per-class Gram matrices
__device__ float d_logdets[K_CLS + 1];         // [0]=full, [1..10]=classes (= logdet/2)

// ---------------- zero scratch ----------------
__global__ void zero_kernel() {
    int total = K_CLS * P * P;
    for (int i = blockIdx.x * blockDim.x + threadIdx.x; i < total;
         i += gridDim.x * blockDim.x)
        d_cov[i] = 0.0f;
    int t = blockIdx.x * blockDim.x + threadIdx.x;
    if (t < K_CLS) d_cursor[t] = 0;
    if (t < K_CLS + 1) d_logdets[t] = 0.0f;
}

// ---------------- class-partition scatter (index lists + counts) ----------------
__global__ void scatter_kernel(const int* __restrict__ y, int m) {
    __shared__ int sCnt[K_CLS], sBase[K_CLS];
    int tid = threadIdx.x;
    int i = blockIdx.x * blockDim.x + tid;
    if (tid < K_CLS) sCnt[tid] = 0;
    __syncthreads();

    int c = 0, local = 0;
    bool act = (i < m);
    if (act) {
        c = y[i];
        if (c < 0) c = 0;
        if (c >= K_CLS) c = K_CLS - 1;
        unsigned mask = __match_any_sync(__activemask(), c);
        int leader = __ffs(mask) - 1;
        int lane = tid & 31;
        int rank = __popc(mask & ((1u << lane) - 1));
        int wb = 0;
        if (lane == leader) wb = atomicAdd(&sCnt[c], __popc(mask));
        wb = __shfl_sync(mask, wb, leader);
        local = wb + rank;
    }
    __syncthreads();
    if (tid < K_CLS) sBase[tid] = atomicAdd(&d_cursor[tid], sCnt[tid]);
    __syncthreads();
    if (act) d_idx[c * CAP + sBase[c] + local] = i;
}

// ---------------- per-class Gram via split-bf16 wmma, symmetric 2-MMA ----------
// v = hi + lo (both bf16).  cov = H^T H + H^T L + (H^T L)^T.
// Compute C1 = H^T H and C2 = H^T L; epilogue adds C2 both straight and
// transposed (bitwise identical to accumulating L^T H separately).
// 512 threads = 16 warps: warp w -> rows 16*(w&7), column half (w>>3)*64.
__global__ void __launch_bounds__(512, 1)
gram_kernel(const float* __restrict__ x) {
    int c = blockIdx.y;
    int n = d_cursor[c];
    const int* idx = d_idx + c * CAP;

    __shared__ __nv_bfloat16 sH[KT][P];   // 16 KB  (hi part)
    __shared__ __nv_bfloat16 sL[KT][P];   // 16 KB  (lo part)
    __shared__ int sIdx[KT];

    int tid = threadIdx.x;
    int w = tid >> 5;
    int lane = tid & 31;
    int wr = w & 7;        // output row strip: rows [16*wr, 16*wr+16)
    int wc = w >> 3;       // column half: cols [64*wc, 64*wc+64)

    wmma::fragment<wmma::matrix_a, 16, 16, 16, __nv_bfloat16, wmma::col_major> faH;
    wmma::fragment<wmma::matrix_b, 16, 16, 16, __nv_bfloat16, wmma::row_major> fbH, fbL;
    wmma::fragment<wmma::accumulator, 16, 16, 16, float> accH[4], accL[4];
#pragma unroll
    for (int t = 0; t < 4; t++) {
        wmma::fill_fragment(accH[t], 0.0f);
        wmma::fill_fragment(accL[t], 0.0f);
    }

    for (int j0 = blockIdx.x * KT; j0 < n; j0 += BPC * KT) {
        __syncthreads();
        if (tid < KT) sIdx[tid] = (j0 + tid < n) ? idx[j0 + tid] : -1;
        __syncthreads();
        // gather rows (fp32), split into hi/lo bf16.  2048 float4 units.
#pragma unroll
        for (int q = 0; q < 4; q++) {
            int u = tid + q * 512;
            int r = u >> 5;               // row within tile
            int c4 = u & 31;              // float4 within row
            int g = sIdx[r];
            float4 v = (g >= 0) ? reinterpret_cast<const float4*>(x)[g * 32 + c4]
                                : make_float4(0.f, 0.f, 0.f, 0.f);
            __nv_bfloat16 hx = __float2bfloat16_rn(v.x);
            __nv_bfloat16 hy = __float2bfloat16_rn(v.y);
            __nv_bfloat16 hz = __float2bfloat16_rn(v.z);
            __nv_bfloat16 hw = __float2bfloat16_rn(v.w);
            __nv_bfloat16 lx = __float2bfloat16_rn(v.x - __bfloat162float(hx));
            __nv_bfloat16 ly = __float2bfloat16_rn(v.y - __bfloat162float(hy));
            __nv_bfloat16 lz = __float2bfloat16_rn(v.z - __bfloat162float(hz));
            __nv_bfloat16 lw = __float2bfloat16_rn(v.w - __bfloat162float(hw));
            *reinterpret_cast<__nv_bfloat162*>(&sH[r][c4 * 4])     = __nv_bfloat162(hx, hy);
            *reinterpret_cast<__nv_bfloat162*>(&sH[r][c4 * 4 + 2]) = __nv_bfloat162(hz, hw);
            *reinterpret_cast<__nv_bfloat162*>(&sL[r][c4 * 4])     = __nv_bfloat162(lx, ly);
            *reinterpret_cast<__nv_bfloat162*>(&sL[r][c4 * 4 + 2]) = __nv_bfloat162(lz, lw);
        }
        __syncthreads();
#pragma unroll
        for (int ks = 0; ks < KT / 16; ks++) {
            wmma::load_matrix_sync(faH, &sH[ks * 16][wr * 16], P);
#pragma unroll
            for (int t = 0; t < 4; t++) {
                int tc = wc * 64 + t * 16;
                wmma::load_matrix_sync(fbH, &sH[ks * 16][tc], P);
                wmma::load_matrix_sync(fbL, &sL[ks * 16][tc], P);
                wmma::mma_sync(accH[t], faH, fbH, accH[t]);
                wmma::mma_sync(accL[t], faH, fbL, accL[t]);
            }
        }
    }

    // epilogue: stage per-warp through smem (reuse sH after sync) -> atomics
    __syncthreads();
    float* stage = reinterpret_cast<float*>(&sH[0][0]) + w * 256;  // 16 warps * 1KB
    float* covc = d_cov + c * P * P;
#pragma unroll
    for (int t = 0; t < 4; t++) {
        int cbase = wc * 64 + t * 16;
        // C1 = H^T H
        wmma::store_matrix_sync(stage, accH[t], 16, wmma::mem_row_major);
        __syncwarp();
        for (int e = lane; e < 256; e += 32) {
            int r = wr * 16 + (e >> 4);
            int col = cbase + (e & 15);
            atomicAdd(&covc[r * P + col], stage[e]);
        }
        __syncwarp();
        // C2 = H^T L, added straight and transposed
        wmma::store_matrix_sync(stage, accL[t], 16, wmma::mem_row_major);
        __syncwarp();
        for (int e = lane; e < 256; e += 32) {
            int r = wr * 16 + (e >> 4);
            int col = cbase + (e & 15);
            float v = stage[e];
            atomicAdd(&covc[r * P + col], v);
            atomicAdd(&covc[col * P + r], v);
        }
        __syncwarp();
    }
}

// ---------------- Cholesky logdet (one block per matrix) ----------------
// Row-major padded A[i*LDP + t] in dynamic smem. Dot products over own row
// (contiguous float4, conflict-free via +4 pad) and pivot row (broadcast).
__global__ void __launch_bounds__(128) chol_kernel(int m) {
    extern __shared__ float A[];  // 128*132 floats = 67.6 KB
    __shared__ float sDiag;
    int b = blockIdx.x;
    int i = threadIdx.x;          // thread == row

    if (b == 0) {
        float scal = (float)P / ((float)m * EPS_C);
        for (int e = i; e < P * P; e += 128) {
            float v = 0.f;
#pragma unroll
            for (int c = 0; c < K_CLS; c++) v += d_cov[c * P * P + e];
            A[(e >> 7) * LDP + (e & 127)] =
                ((e % (P + 1)) == 0 ? 1.0f : 0.0f) + scal * v;
        }
    } else {
        int c = b - 1;
        int n = d_cursor[c];
        int ns = n > 0 ? n : 1;
        float scal = (float)P / ((float)ns * EPS_C);
        for (int e = i; e < P * P; e += 128)
            A[(e >> 7) * LDP + (e & 127)] =
                ((e % (P + 1)) == 0 ? 1.0f : 0.0f) + scal * d_cov[c * P * P + e];
    }
    __syncthreads();

    float logsum = 0.0f;
    for (int j = 0; j < P; j++) {
        float s = 0.0f;
        if (i >= j) {
            const float4* ri = reinterpret_cast<const float4*>(A + i * LDP);
            const float4* rj = reinterpret_cast<const float4*>(A + j * LDP);
            float a0 = 0.f, a1 = 0.f, a2 = 0.f, a3 = 0.f;
            int n4 = j >> 2;
#pragma unroll 4
            for (int t = 0; t < n4; t++) {
                float4 u = ri[t];
                float4 v = rj[t];
                a0 += u.x * v.x; a1 += u.y * v.y;
                a2 += u.z * v.z; a3 += u.w * v.w;
            }
            for (int t = n4 * 4; t < j; t++)
                a0 += A[i * LDP + t] * A[j * LDP + t];
            s = A[i * LDP + j] - ((a0 + a1) + (a2 + a3));
            if (i == j) sDiag = s;
        }
        __syncthreads();
        float dd = sDiag;
        float d = sqrtf(dd);
        logsum += 0.5f * logf(dd);
        if (i > j)       A[i * LDP + j] = s / d;
        else if (i == j) A[i * LDP + j] = d;
        __syncthreads();
    }
    if (i == 0) d_logdets[b] = logsum;   // = slogdet/2
}

// ---------------- final reduction to 4 scalars ----------------
__global__ void finalize_kernel(float* __restrict__ out, int m) {
    if (threadIdx.x == 0 && blockIdx.x == 0) {
        float disc = d_logdets[0];   // discrimn_empi == discrimn_theo (GAM1 = 1)
        float comp = 0.0f;
#pragma unroll
        for (int c = 0; c < K_CLS; c++) {
            int n = d_cursor[c];
            if (n > 0) comp += d_logdets[1 + c] * ((float)n / (float)m);
        }
        out[0] = -disc + comp;  // GAM2 = 1
        out[1] = disc;
        out[2] = disc;
        out[3] = comp;
    }
}

// ---------------- launch ----------------
extern "C" void kernel_launch(void* const* d_in, const int* in_sizes, int n_in,
                              void* d_out, int out_size) {
    const float* x = (const float*)d_in[0];
    const int*   y = (const int*)d_in[1];
    int m = in_sizes[0] / P;

    cudaFuncSetAttribute(chol_kernel,
                         cudaFuncAttributeMaxDynamicSharedMemorySize, 128 * LDP * 4);

    zero_kernel<<<256, 256>>>();
    scatter_kernel<<<(m + 255) / 256, 256>>>(y, m);
    gram_kernel<<<dim3(BPC, K_CLS), 512>>>(x);
    chol_kernel<<<K_CLS + 1, P, 128 * LDP * 4>>>(m);
    finalize_kernel<<<1, 32>>>((float*)d_out, m);
}

// round 5
// speedup vs baseline: 1.0811x; 1.0204x over previous
#include <cuda_runtime.h>
#include <cuda_bf16.h>
#include <mma.h>

using namespace nvcuda;

#define K_CLS 10
#define P 128
#define CAP 262144          // max rows (m)
#define EPS_C 0.01f
#define KT 64               // rows per gram tile
#define BPC 14              // blocks per class (14*10=140 <= 148 SMs, one wave)
#define LDP 132             // padded row stride for Cholesky smem (floats)

// ---------------- device globals (no allocations allowed) ----------------
__device__ int   d_cursor[K_CLS];              // per-class counts / cursors
__device__ int   d_idx[K_CLS * CAP];           // per-class row index lists
__device__ float d_cov[K_CLS * P * P];         // per-class Gram matrices
__device__ float d_logdets[K_CLS + 1];         // [0]=full, [1..10]=classes (= logdet/2)

// ---------------- zero scratch ----------------
__global__ void zero_kernel() {
    int total = K_CLS * P * P;
    for (int i = blockIdx.x * blockDim.x + threadIdx.x; i < total;
         i += gridDim.x * blockDim.x)
        d_cov[i] = 0.0f;
    int t = blockIdx.x * blockDim.x + threadIdx.x;
    if (t < K_CLS) d_cursor[t] = 0;
    if (t < K_CLS + 1) d_logdets[t] = 0.0f;
}

// ---------------- class-partition scatter (index lists + counts) ----------------
__global__ void scatter_kernel(const int* __restrict__ y, int m) {
    __shared__ int sCnt[K_CLS], sBase[K_CLS];
    int tid = threadIdx.x;
    int i = blockIdx.x * blockDim.x + tid;
    if (tid < K_CLS) sCnt[tid] = 0;
    __syncthreads();

    int c = 0, local = 0;
    bool act = (i < m);
    if (act) {
        c = y[i];
        if (c < 0) c = 0;
        if (c >= K_CLS) c = K_CLS - 1;
        unsigned mask = __match_any_sync(__activemask(), c);
        int leader = __ffs(mask) - 1;
        int lane = tid & 31;
        int rank = __popc(mask & ((1u << lane) - 1));
        int wb = 0;
        if (lane == leader) wb = atomicAdd(&sCnt[c], __popc(mask));
        wb = __shfl_sync(mask, wb, leader);
        local = wb + rank;
    }
    __syncthreads();
    if (tid < K_CLS) sBase[tid] = atomicAdd(&d_cursor[tid], sCnt[tid]);
    __syncthreads();
    if (act) d_idx[c * CAP + sBase[c] + local] = i;
}

// ---------------- per-class Gram via split-bf16 wmma, symmetric 2-MMA ----------
// v = hi + lo (both bf16).  cov = H^T H + H^T L + (H^T L)^T.
// Compute C1 = H^T H and C2 = H^T L; epilogue adds C2 both straight and
// transposed (bitwise identical to accumulating L^T H separately).
// 512 threads = 16 warps: warp w -> rows 16*(w&7), column half (w>>3)*64.
__global__ void __launch_bounds__(512, 1)
gram_kernel(const float* __restrict__ x) {
    int c = blockIdx.y;
    int n = d_cursor[c];
    const int* idx = d_idx + c * CAP;

    __shared__ __nv_bfloat16 sH[KT][P];   // 16 KB  (hi part)
    __shared__ __nv_bfloat16 sL[KT][P];   // 16 KB  (lo part)
    __shared__ int sIdx[KT];

    int tid = threadIdx.x;
    int w = tid >> 5;
    int lane = tid & 31;
    int wr = w & 7;        // output row strip: rows [16*wr, 16*wr+16)
    int wc = w >> 3;       // column half: cols [64*wc, 64*wc+64)

    wmma::fragment<wmma::matrix_a, 16, 16, 16, __nv_bfloat16, wmma::col_major> faH;
    wmma::fragment<wmma::matrix_b, 16, 16, 16, __nv_bfloat16, wmma::row_major> fbH, fbL;
    wmma::fragment<wmma::accumulator, 16, 16, 16, float> accH[4], accL[4];
#pragma unroll
    for (int t = 0; t < 4; t++) {
        wmma::fill_fragment(accH[t], 0.0f);
        wmma::fill_fragment(accL[t], 0.0f);
    }

    for (int j0 = blockIdx.x * KT; j0 < n; j0 += BPC * KT) {
        __syncthreads();
        if (tid < KT) sIdx[tid] = (j0 + tid < n) ? idx[j0 + tid] : -1;
        __syncthreads();
        // gather rows (fp32), split into hi/lo bf16.  2048 float4 units.
#pragma unroll
        for (int q = 0; q < 4; q++) {
            int u = tid + q * 512;
            int r = u >> 5;               // row within tile
            int c4 = u & 31;              // float4 within row
            int g = sIdx[r];
            float4 v = (g >= 0) ? reinterpret_cast<const float4*>(x)[g * 32 + c4]
                                : make_float4(0.f, 0.f, 0.f, 0.f);
            __nv_bfloat16 hx = __float2bfloat16_rn(v.x);
            __nv_bfloat16 hy = __float2bfloat16_rn(v.y);
            __nv_bfloat16 hz = __float2bfloat16_rn(v.z);
            __nv_bfloat16 hw = __float2bfloat16_rn(v.w);
            __nv_bfloat16 lx = __float2bfloat16_rn(v.x - __bfloat162float(hx));
            __nv_bfloat16 ly = __float2bfloat16_rn(v.y - __bfloat162float(hy));
            __nv_bfloat16 lz = __float2bfloat16_rn(v.z - __bfloat162float(hz));
            __nv_bfloat16 lw = __float2bfloat16_rn(v.w - __bfloat162float(hw));
            *reinterpret_cast<__nv_bfloat162*>(&sH[r][c4 * 4])     = __nv_bfloat162(hx, hy);
            *reinterpret_cast<__nv_bfloat162*>(&sH[r][c4 * 4 + 2]) = __nv_bfloat162(hz, hw);
            *reinterpret_cast<__nv_bfloat162*>(&sL[r][c4 * 4])     = __nv_bfloat162(lx, ly);
            *reinterpret_cast<__nv_bfloat162*>(&sL[r][c4 * 4 + 2]) = __nv_bfloat162(lz, lw);
        }
        __syncthreads();
#pragma unroll
        for (int ks = 0; ks < KT / 16; ks++) {
            wmma::load_matrix_sync(faH, &sH[ks * 16][wr * 16], P);
#pragma unroll
            for (int t = 0; t < 4; t++) {
                int tc = wc * 64 + t * 16;
                wmma::load_matrix_sync(fbH, &sH[ks * 16][tc], P);
                wmma::load_matrix_sync(fbL, &sL[ks * 16][tc], P);
                wmma::mma_sync(accH[t], faH, fbH, accH[t]);
                wmma::mma_sync(accL[t], faH, fbL, accL[t]);
            }
        }
    }

    // epilogue: stage per-warp through smem (reuse sH after sync) -> atomics
    __syncthreads();
    float* stage = reinterpret_cast<float*>(&sH[0][0]) + w * 256;  // 16 warps * 1KB
    float* covc = d_cov + c * P * P;
#pragma unroll
    for (int t = 0; t < 4; t++) {
        int cbase = wc * 64 + t * 16;
        // C1 = H^T H
        wmma::store_matrix_sync(stage, accH[t], 16, wmma::mem_row_major);
        __syncwarp();
        for (int e = lane; e < 256; e += 32) {
            int r = wr * 16 + (e >> 4);
            int col = cbase + (e & 15);
            atomicAdd(&covc[r * P + col], stage[e]);
        }
        __syncwarp();
        // C2 = H^T L, added straight and transposed
        wmma::store_matrix_sync(stage, accL[t], 16, wmma::mem_row_major);
        __syncwarp();
        for (int e = lane; e < 256; e += 32) {
            int r = wr * 16 + (e >> 4);
            int col = cbase + (e & 15);
            float v = stage[e];
            atomicAdd(&covc[r * P + col], v);
            atomicAdd(&covc[col * P + r], v);
        }
        __syncwarp();
    }
}

// ---------------- Cholesky logdet (one block per matrix) ----------------
// Row-major padded A[i*LDP + t] in dynamic smem. Dot products over own row
// (contiguous float4, conflict-free via +4 pad) and pivot row (broadcast).
__global__ void __launch_bounds__(128) chol_kernel(int m) {
    extern __shared__ float A[];  // 128*132 floats = 67.6 KB
    __shared__ float sDiag;
    int b = blockIdx.x;
    int i = threadIdx.x;          // thread == row

    if (b == 0) {
        float scal = (float)P / ((float)m * EPS_C);
        for (int e = i; e < P * P; e += 128) {
            float v = 0.f;
#pragma unroll
            for (int c = 0; c < K_CLS; c++) v += d_cov[c * P * P + e];
            A[(e >> 7) * LDP + (e & 127)] =
                ((e % (P + 1)) == 0 ? 1.0f : 0.0f) + scal * v;
        }
    } else {
        int c = b - 1;
        int n = d_cursor[c];
        int ns = n > 0 ? n : 1;
        float scal = (float)P / ((float)ns * EPS_C);
        for (int e = i; e < P * P; e += 128)
            A[(e >> 7) * LDP + (e & 127)] =
                ((e % (P + 1)) == 0 ? 1.0f : 0.0f) + scal * d_cov[c * P * P + e];
    }
    __syncthreads();

    float logsum = 0.0f;
    for (int j = 0; j < P; j++) {
        float s = 0.0f;
        if (i >= j) {
            const float4* ri = reinterpret_cast<const float4*>(A + i * LDP);
            const float4* rj = reinterpret_cast<const float4*>(A + j * LDP);
            float a0 = 0.f, a1 = 0.f, a2 = 0.f, a3 = 0.f;
            int n4 = j >> 2;
#pragma unroll 4
            for (int t = 0; t < n4; t++) {
                float4 u = ri[t];
                float4 v = rj[t];
                a0 += u.x * v.x; a1 += u.y * v.y;
                a2 += u.z * v.z; a3 += u.w * v.w;
            }
            for (int t = n4 * 4; t < j; t++)
                a0 += A[i * LDP + t] * A[j * LDP + t];
            s = A[i * LDP + j] - ((a0 + a1) + (a2 + a3));
            if (i == j) sDiag = s;
        }
        __syncthreads();
        float dd = sDiag;
        float d = sqrtf(dd);
        logsum += 0.5f * logf(dd);
        if (i > j)       A[i * LDP + j] = s / d;
        else if (i == j) A[i * LDP + j] = d;
        __syncthreads();
    }
    if (i == 0) d_logdets[b] = logsum;   // = slogdet/2
}

// ---------------- final reduction to 4 scalars ----------------
__global__ void finalize_kernel(float* __restrict__ out, int m) {
    if (threadIdx.x == 0 && blockIdx.x == 0) {
        float disc = d_logdets[0];   // discrimn_empi == discrimn_theo (GAM1 = 1)
        float comp = 0.0f;
#pragma unroll
        for (int c = 0; c < K_CLS; c++) {
            int n = d_cursor[c];
            if (n > 0) comp += d_logdets[1 + c] * ((float)n / (float)m);
        }
        out[0] = -disc + comp;  // GAM2 = 1
        out[1] = disc;
        out[2] = disc;
        out[3] = comp;
    }
}

// ---------------- launch ----------------
extern "C" void kernel_launch(void* const* d_in, const int* in_sizes, int n_in,
                              void* d_out, int out_size) {
    const float* x = (const float*)d_in[0];
    const int*   y = (const int*)d_in[1];
    int m = in_sizes[0] / P;

    cudaFuncSetAttribute(chol_kernel,
                         cudaFuncAttributeMaxDynamicSharedMemorySize, 128 * LDP * 4);

    zero_kernel<<<256, 256>>>();
    scatter_kernel<<<(m + 255) / 256, 256>>>(y, m);
    gram_kernel<<<dim3(BPC, K_CLS), 512>>>(x);
    chol_kernel<<<K_CLS + 1, P, 128 * LDP * 4>>>(m);
    finalize_kernel<<<1, 32>>>((float*)d_out, m);
}

// round 6
// speedup vs baseline: 1.0846x; 1.0032x over previous
#include <cuda_runtime.h>
#include <cuda_bf16.h>
#include <mma.h>

using namespace nvcuda;

#define K_CLS 10
#define P 128
#define CAP 262144          // max rows (m)
#define EPS_C 0.01f
#define KT 64               // rows per gram tile
#define BPC 14              // blocks per class (14*10=140 <= 148 SMs, one wave)
#define LDP 132             // padded row stride for Cholesky smem (floats)

// ---------------- device globals (no allocations allowed) ----------------
__device__ int   d_cursor[K_CLS];              // per-class counts / cursors
__device__ int   d_idx[K_CLS * CAP];           // per-class row index lists
__device__ float d_cov[K_CLS * P * P];         // per-class Gram matrices
__device__ float d_logdets[K_CLS + 1];         // [0]=full, [1..10]=classes (= logdet/2)

// ---------------- zero scratch ----------------
__global__ void zero_kernel() {
    int total = K_CLS * P * P;
    for (int i = blockIdx.x * blockDim.x + threadIdx.x; i < total;
         i += gridDim.x * blockDim.x)
        d_cov[i] = 0.0f;
    int t = blockIdx.x * blockDim.x + threadIdx.x;
    if (t < K_CLS) d_cursor[t] = 0;
    if (t < K_CLS + 1) d_logdets[t] = 0.0f;
}

// ---------------- class-partition scatter (index lists + counts) ----------------
__global__ void scatter_kernel(const int* __restrict__ y, int m) {
    __shared__ int sCnt[K_CLS], sBase[K_CLS];
    int tid = threadIdx.x;
    int i = blockIdx.x * blockDim.x + tid;
    if (tid < K_CLS) sCnt[tid] = 0;
    __syncthreads();

    int c = 0, local = 0;
    bool act = (i < m);
    if (act) {
        c = y[i];
        if (c < 0) c = 0;
        if (c >= K_CLS) c = K_CLS - 1;
        unsigned mask = __match_any_sync(__activemask(), c);
        int leader = __ffs(mask) - 1;
        int lane = tid & 31;
        int rank = __popc(mask & ((1u << lane) - 1));
        int wb = 0;
        if (lane == leader) wb = atomicAdd(&sCnt[c], __popc(mask));
        wb = __shfl_sync(mask, wb, leader);
        local = wb + rank;
    }
    __syncthreads();
    if (tid < K_CLS) sBase[tid] = atomicAdd(&d_cursor[tid], sCnt[tid]);
    __syncthreads();
    if (act) d_idx[c * CAP + sBase[c] + local] = i;
}

// ---------------- per-class Gram via split-bf16 wmma, symmetric 2-MMA ----------
// v = hi + lo (both bf16).  cov = H^T H + H^T L + (H^T L)^T.
// Compute C1 = H^T H and C2 = H^T L; epilogue adds C2 both straight and
// transposed (bitwise identical to accumulating L^T H separately).
// 512 threads = 16 warps: warp w -> rows 16*(w&7), column half (w>>3)*64.
__global__ void __launch_bounds__(512, 1)
gram_kernel(const float* __restrict__ x) {
    int c = blockIdx.y;
    int n = d_cursor[c];
    const int* idx = d_idx + c * CAP;

    __shared__ __nv_bfloat16 sH[KT][P];   // 16 KB  (hi part)
    __shared__ __nv_bfloat16 sL[KT][P];   // 16 KB  (lo part)
    __shared__ int sIdx[KT];

    int tid = threadIdx.x;
    int w = tid >> 5;
    int lane = tid & 31;
    int wr = w & 7;        // output row strip: rows [16*wr, 16*wr+16)
    int wc = w >> 3;       // column half: cols [64*wc, 64*wc+64)

    wmma::fragment<wmma::matrix_a, 16, 16, 16, __nv_bfloat16, wmma::col_major> faH;
    wmma::fragment<wmma::matrix_b, 16, 16, 16, __nv_bfloat16, wmma::row_major> fbH, fbL;
    wmma::fragment<wmma::accumulator, 16, 16, 16, float> accH[4], accL[4];
#pragma unroll
    for (int t = 0; t < 4; t++) {
        wmma::fill_fragment(accH[t], 0.0f);
        wmma::fill_fragment(accL[t], 0.0f);
    }

    for (int j0 = blockIdx.x * KT; j0 < n; j0 += BPC * KT) {
        __syncthreads();
        if (tid < KT) sIdx[tid] = (j0 + tid < n) ? idx[j0 + tid] : -1;
        __syncthreads();
        // gather rows (fp32), split into hi/lo bf16.  2048 float4 units.
#pragma unroll
        for (int q = 0; q < 4; q++) {
            int u = tid + q * 512;
            int r = u >> 5;               // row within tile
            int c4 = u & 31;              // float4 within row
            int g = sIdx[r];
            float4 v = (g >= 0) ? reinterpret_cast<const float4*>(x)[g * 32 + c4]
                                : make_float4(0.f, 0.f, 0.f, 0.f);
            __nv_bfloat16 hx = __float2bfloat16_rn(v.x);
            __nv_bfloat16 hy = __float2bfloat16_rn(v.y);
            __nv_bfloat16 hz = __float2bfloat16_rn(v.z);
            __nv_bfloat16 hw = __float2bfloat16_rn(v.w);
            __nv_bfloat16 lx = __float2bfloat16_rn(v.x - __bfloat162float(hx));
            __nv_bfloat16 ly = __float2bfloat16_rn(v.y - __bfloat162float(hy));
            __nv_bfloat16 lz = __float2bfloat16_rn(v.z - __bfloat162float(hz));
            __nv_bfloat16 lw = __float2bfloat16_rn(v.w - __bfloat162float(hw));
            *reinterpret_cast<__nv_bfloat162*>(&sH[r][c4 * 4])     = __nv_bfloat162(hx, hy);
            *reinterpret_cast<__nv_bfloat162*>(&sH[r][c4 * 4 + 2]) = __nv_bfloat162(hz, hw);
            *reinterpret_cast<__nv_bfloat162*>(&sL[r][c4 * 4])     = __nv_bfloat162(lx, ly);
            *reinterpret_cast<__nv_bfloat162*>(&sL[r][c4 * 4 + 2]) = __nv_bfloat162(lz, lw);
        }
        __syncthreads();
#pragma unroll
        for (int ks = 0; ks < KT / 16; ks++) {
            wmma::load_matrix_sync(faH, &sH[ks * 16][wr * 16], P);
#pragma unroll
            for (int t = 0; t < 4; t++) {
                int tc = wc * 64 + t * 16;
                wmma::load_matrix_sync(fbH, &sH[ks * 16][tc], P);
                wmma::load_matrix_sync(fbL, &sL[ks * 16][tc], P);
                wmma::mma_sync(accH[t], faH, fbH, accH[t]);
                wmma::mma_sync(accL[t], faH, fbL, accL[t]);
            }
        }
    }

    // epilogue: stage per-warp through smem (reuse sH after sync) -> atomics
    __syncthreads();
    float* stage = reinterpret_cast<float*>(&sH[0][0]) + w * 256;  // 16 warps * 1KB
    float* covc = d_cov + c * P * P;
#pragma unroll
    for (int t = 0; t < 4; t++) {
        int cbase = wc * 64 + t * 16;
        // C1 = H^T H
        wmma::store_matrix_sync(stage, accH[t], 16, wmma::mem_row_major);
        __syncwarp();
        for (int e = lane; e < 256; e += 32) {
            int r = wr * 16 + (e >> 4);
            int col = cbase + (e & 15);
            atomicAdd(&covc[r * P + col], stage[e]);
        }
        __syncwarp();
        // C2 = H^T L, added straight and transposed
        wmma::store_matrix_sync(stage, accL[t], 16, wmma::mem_row_major);
        __syncwarp();
        for (int e = lane; e < 256; e += 32) {
            int r = wr * 16 + (e >> 4);
            int col = cbase + (e & 15);
            float v = stage[e];
            atomicAdd(&covc[r * P + col], v);
            atomicAdd(&covc[col * P + r], v);
        }
        __syncwarp();
    }
}

// ---------------- Cholesky logdet (one block per matrix) ----------------
// Row-major padded A[i*LDP + t] in dynamic smem. Dot products over own row
// (contiguous float4, conflict-free via +4 pad) and pivot row (broadcast).
__global__ void __launch_bounds__(128) chol_kernel(int m) {
    extern __shared__ float A[];  // 128*132 floats = 67.6 KB
    __shared__ float sDiag;
    int b = blockIdx.x;
    int i = threadIdx.x;          // thread == row

    if (b == 0) {
        float scal = (float)P / ((float)m * EPS_C);
        for (int e = i; e < P * P; e += 128) {
            float v = 0.f;
#pragma unroll
            for (int c = 0; c < K_CLS; c++) v += d_cov[c * P * P + e];
            A[(e >> 7) * LDP + (e & 127)] =
                ((e % (P + 1)) == 0 ? 1.0f : 0.0f) + scal * v;
        }
    } else {
        int c = b - 1;
        int n = d_cursor[c];
        int ns = n > 0 ? n : 1;
        float scal = (float)P / ((float)ns * EPS_C);
        for (int e = i; e < P * P; e += 128)
            A[(e >> 7) * LDP + (e & 127)] =
                ((e % (P + 1)) == 0 ? 1.0f : 0.0f) + scal * d_cov[c * P * P + e];
    }
    __syncthreads();

    float logsum = 0.0f;
    for (int j = 0; j < P; j++) {
        float s = 0.0f;
        if (i >= j) {
            const float4* ri = reinterpret_cast<const float4*>(A + i * LDP);
            const float4* rj = reinterpret_cast<const float4*>(A + j * LDP);
            float a0 = 0.f, a1 = 0.f, a2 = 0.f, a3 = 0.f;
            int n4 = j >> 2;
#pragma unroll 4
            for (int t = 0; t < n4; t++) {
                float4 u = ri[t];
                float4 v = rj[t];
                a0 += u.x * v.x; a1 += u.y * v.y;
                a2 += u.z * v.z; a3 += u.w * v.w;
            }
            for (int t = n4 * 4; t < j; t++)
                a0 += A[i * LDP + t] * A[j * LDP + t];
            s = A[i * LDP + j] - ((a0 + a1) + (a2 + a3));
            if (i == j) sDiag = s;
        }
        __syncthreads();
        float dd = sDiag;
        float d = sqrtf(dd);
        logsum += 0.5f * logf(dd);
        if (i > j)       A[i * LDP + j] = s / d;
        else if (i == j) A[i * LDP + j] = d;
        __syncthreads();
    }
    if (i == 0) d_logdets[b] = logsum;   // = slogdet/2
}

// ---------------- final reduction to 4 scalars ----------------
__global__ void finalize_kernel(float* __restrict__ out, int m) {
    if (threadIdx.x == 0 && blockIdx.x == 0) {
        float disc = d_logdets[0];   // discrimn_empi == discrimn_theo (GAM1 = 1)
        float comp = 0.0f;
#pragma unroll
        for (int c = 0; c < K_CLS; c++) {
            int n = d_cursor[c];
            if (n > 0) comp += d_logdets[1 + c] * ((float)n / (float)m);
        }
        out[0] = -disc + comp;  // GAM2 = 1
        out[1] = disc;
        out[2] = disc;
        out[3] = comp;
    }
}

// ---------------- launch ----------------
extern "C" void kernel_launch(void* const* d_in, const int* in_sizes, int n_in,
                              void* d_out, int out_size) {
    const float* x = (const float*)d_in[0];
    const int*   y = (const int*)d_in[1];
    int m = in_sizes[0] / P;

    cudaFuncSetAttribute(chol_kernel,
                         cudaFuncAttributeMaxDynamicSharedMemorySize, 128 * LDP * 4);

    zero_kernel<<<256, 256>>>();
    scatter_kernel<<<(m + 255) / 256, 256>>>(y, m);
    gram_kernel<<<dim3(BPC, K_CLS), 512>>>(x);
    chol_kernel<<<K_CLS + 1, P, 128 * LDP * 4>>>(m);
    finalize_kernel<<<1, 32>>>((float*)d_out, m);
}